// round 1
// baseline (speedup 1.0000x reference)
#include <cuda_runtime.h>
#include <cstdint>
#include <cstddef>

// Problem shapes (fixed by the reference)
#define BATCH   8
#define SEQ     4096
#define CDIM    768
#define EDIM    768
#define MTOK    (BATCH*SEQ)          // 32768 rows
#define QKVCOLS (3*EDIM)             // 2304

// ---------------- scratch (static device globals; no allocs) ----------------
__device__ float g_qkv[(size_t)MTOK * QKVCOLS];   // 302 MB
__device__ float g_mu[MTOK];
__device__ float g_rstd[MTOK];
__device__ float g_invnk[MTOK];
__device__ float g_invnq[MTOK];
__device__ float g_mu2[MTOK];
__device__ float g_rstd2[MTOK];
__device__ float g_kv[BATCH * EDIM];

// ---------------- helpers ----------------
__device__ __forceinline__ float wsum(float v) {
#pragma unroll
    for (int o = 16; o > 0; o >>= 1) v += __shfl_xor_sync(0xFFFFFFFFu, v, o);
    return v;
}

__device__ __forceinline__ uint32_t tf32u(float x) {
    uint32_t u;
    asm("cvt.rna.tf32.f32 %0, %1;" : "=r"(u) : "f"(x));
    return u;
}
__device__ __forceinline__ float tf32f(float x) { return __uint_as_float(tf32u(x)); }

// ---------------- K1: LayerNorm stats (warp per token) ----------------
__global__ void ln_stats_kernel(const float* __restrict__ x,
                                float* __restrict__ mu, float* __restrict__ rstd) {
    int m = blockIdx.x * 8 + (threadIdx.x >> 5);
    int lane = threadIdx.x & 31;
    const float* row = x + (size_t)m * CDIM;
    float v[24];
    float s = 0.f;
#pragma unroll
    for (int i = 0; i < 24; i++) { v[i] = row[lane + 32 * i]; s += v[i]; }
    s = wsum(s);
    float mean = s * (1.0f / CDIM);
    float ss = 0.f;
#pragma unroll
    for (int i = 0; i < 24; i++) { float d = v[i] - mean; ss += d * d; }
    ss = wsum(ss);
    if (lane == 0) {
        mu[m] = mean;
        rstd[m] = rsqrtf(ss * (1.0f / CDIM) + 1e-5f);
    }
}

// ---------------- K3a: per-token inverse L2 norm of k (warp per token) ----------------
__global__ void knorm_kernel(const float* __restrict__ qkv, float* __restrict__ invnk) {
    int m = blockIdx.x * 8 + (threadIdx.x >> 5);
    int lane = threadIdx.x & 31;
    const float* row = qkv + (size_t)m * QKVCOLS + EDIM;   // k slice
    float ss = 0.f;
#pragma unroll
    for (int i = 0; i < 24; i++) { float t = row[lane + 32 * i]; ss += t * t; }
    ss = wsum(ss);
    if (lane == 0) invnk[m] = 1.0f / fmaxf(sqrtf(ss), 1e-12f);
}

// ---------------- zero g_kv ----------------
__global__ void zero_kv_kernel(float* __restrict__ kv) {
    kv[blockIdx.x * EDIM + threadIdx.x] = 0.f;
}

// ---------------- K3b: kv accumulation (streaming, partial sums + atomics) ----------------
__global__ void kv_acc_kernel(const float* __restrict__ qkv,
                              const float* __restrict__ invnk,
                              float* __restrict__ kv) {
    int b = blockIdx.y, chunk = blockIdx.x, tid = threadIdx.x;
    float a0 = 0.f, a1 = 0.f, a2 = 0.f;
    int m0 = b * SEQ + chunk * 128;
    for (int t = 0; t < 128; t++) {
        size_t base = (size_t)(m0 + t) * QKVCOLS;
        float inv = __ldg(invnk + m0 + t);
        const float* kr = qkv + base + EDIM;
        const float* vr = qkv + base + 2 * EDIM;
        a0 += kr[tid]       * inv * vr[tid];
        a1 += kr[tid + 256] * inv * vr[tid + 256];
        a2 += kr[tid + 512] * inv * vr[tid + 512];
    }
    atomicAdd(&kv[b * EDIM + tid],       a0);
    atomicAdd(&kv[b * EDIM + tid + 256], a1);
    atomicAdd(&kv[b * EDIM + tid + 512], a2);
}

// ---------------- K4: q stats -> invnq, mu2, rstd2 (warp per token) ----------------
// attn_e = q_e * kv_e / max(||q||, eps). Mean/var derived from Sum(q*kv), Sum(q^2 kv^2).
__global__ void qstats_kernel(const float* __restrict__ qkv,
                              const float* __restrict__ kv,
                              float* __restrict__ invnq,
                              float* __restrict__ mu2,
                              float* __restrict__ rstd2) {
    int m = blockIdx.x * 8 + (threadIdx.x >> 5);
    int lane = threadIdx.x & 31;
    const float* qr = qkv + (size_t)m * QKVCOLS;
    const float* kvr = kv + (m >> 12) * EDIM;   // m/4096 = batch
    float sq = 0.f, s1 = 0.f, s2 = 0.f;
#pragma unroll
    for (int i = 0; i < 24; i++) {
        int e = lane + 32 * i;
        float q = qr[e];
        float c = kvr[e];
        sq += q * q;
        float a = q * c;
        s1 += a;
        s2 += a * a;
    }
    sq = wsum(sq); s1 = wsum(s1); s2 = wsum(s2);
    if (lane == 0) {
        float inv = 1.0f / fmaxf(sqrtf(sq), 1e-12f);
        float mean = s1 * inv * (1.0f / EDIM);
        float msq = s2 * inv * inv * (1.0f / EDIM);
        float var = fmaxf(msq - mean * mean, 0.f);
        invnq[m] = inv;
        mu2[m] = mean;
        rstd2[m] = rsqrtf(var + 1e-5f);
    }
}

// ---------------- tf32 mma GEMM with fused A transform ----------------
// MODE 0: A[m][k] = (x[m][k]-mu[m])*rstd[m]*g[k]+b[k]      (LN-in fused)
// MODE 1: A[m][k] = (q[m][k]*kv[b][k]*invnq[m]-mu2[m])*rstd2[m]*g[k]+b[k]  (attn+LN-out fused)
#define BM 128
#define BN 128
#define BK 16

__device__ __forceinline__ void mma_tf32(float* c, const uint32_t* a, const uint32_t* b) {
    asm volatile(
        "mma.sync.aligned.m16n8k8.row.col.f32.tf32.tf32.f32 "
        "{%0,%1,%2,%3}, {%4,%5,%6,%7}, {%8,%9}, {%0,%1,%2,%3};"
        : "+f"(c[0]), "+f"(c[1]), "+f"(c[2]), "+f"(c[3])
        : "r"(a[0]), "r"(a[1]), "r"(a[2]), "r"(a[3]), "r"(b[0]), "r"(b[1]));
}

template <int MODE>
__global__ void __launch_bounds__(256)
gemm_tf32_kernel(const float* __restrict__ A, int lda,
                 const float* __restrict__ Bm, int ncols,
                 float* __restrict__ Cm,
                 const float* __restrict__ gvec, const float* __restrict__ bvec,
                 const float* __restrict__ r0,   // mu | invnq
                 const float* __restrict__ r1,   // rstd | mu2
                 const float* __restrict__ r2,   // - | rstd2
                 const float* __restrict__ kvp)  // - | kv
{
    __shared__ float As[2][BK][BM + 4];   // [k][m]
    __shared__ float Bs[2][BK][BN + 4];   // [k][n]

    const int tid = threadIdx.x;
    const int lane = tid & 31, wid = tid >> 5;
    const int gid = lane >> 2, tig = lane & 3;
    const int wm = (wid >> 2) * 64;       // warp M offset (2 warps in M)
    const int wn = (wid & 3) * 32;        // warp N offset (4 warps in N)
    const int bm0 = blockIdx.y * BM, bn0 = blockIdx.x * BN;
    const int KT = CDIM / BK;             // 48

    float acc[4][4][4];
#pragma unroll
    for (int i = 0; i < 4; i++)
#pragma unroll
        for (int j = 0; j < 4; j++)
#pragma unroll
            for (int r = 0; r < 4; r++) acc[i][j][r] = 0.f;

    float4 ar[2], br[2];

    // ---- load tile kt into registers ----
    auto load_tile = [&](int kt) {
        int k0 = kt * BK;
#pragma unroll
        for (int i = 0; i < 2; i++) {
            int f = tid + i * 256;
            int ml = f >> 2, kq = (f & 3) << 2;
            int m = bm0 + ml;
            float4 xa = *(const float4*)(A + (size_t)m * lda + (k0 + kq));
            float o[4];
            if (MODE == 0) {
                float mu = __ldg(r0 + m), rs = __ldg(r1 + m);
#pragma unroll
                for (int j = 0; j < 4; j++) {
                    int k = k0 + kq + j;
                    float xv = (&xa.x)[j];
                    o[j] = (xv - mu) * rs * __ldg(gvec + k) + __ldg(bvec + k);
                }
            } else {
                float inv = __ldg(r0 + m), m2 = __ldg(r1 + m), rs2 = __ldg(r2 + m);
                const float* kvr = kvp + ((m >> 12) * EDIM);
#pragma unroll
                for (int j = 0; j < 4; j++) {
                    int k = k0 + kq + j;
                    float xv = (&xa.x)[j];
                    o[j] = (xv * __ldg(kvr + k) * inv - m2) * rs2 * __ldg(gvec + k) + __ldg(bvec + k);
                }
            }
            ar[i] = make_float4(o[0], o[1], o[2], o[3]);
        }
#pragma unroll
        for (int i = 0; i < 2; i++) {
            int f = tid + i * 256;
            int kr = f >> 5, nq = (f & 31) << 2;
            br[i] = *(const float4*)(Bm + (size_t)(k0 + kr) * ncols + bn0 + nq);
        }
    };

    // ---- store registers into smem buffer (tf32-rounded) ----
    auto store_tile = [&](int buf) {
#pragma unroll
        for (int i = 0; i < 2; i++) {
            int f = tid + i * 256;
            int ml = f >> 2, kq = (f & 3) << 2;
            As[buf][kq + 0][ml] = tf32f(ar[i].x);
            As[buf][kq + 1][ml] = tf32f(ar[i].y);
            As[buf][kq + 2][ml] = tf32f(ar[i].z);
            As[buf][kq + 3][ml] = tf32f(ar[i].w);
        }
#pragma unroll
        for (int i = 0; i < 2; i++) {
            int f = tid + i * 256;
            int kr = f >> 5, nq = (f & 31) << 2;
            float4 t = make_float4(tf32f(br[i].x), tf32f(br[i].y), tf32f(br[i].z), tf32f(br[i].w));
            *(float4*)&Bs[buf][kr][nq] = t;
        }
    };

    // ---- compute one smem tile ----
    auto compute = [&](int buf) {
#pragma unroll
        for (int kk = 0; kk < 2; kk++) {
            int kb = kk * 8;
            uint32_t af[4][4], bf[4][2];
#pragma unroll
            for (int mf = 0; mf < 4; mf++) {
                int mb = wm + mf * 16;
                af[mf][0] = __float_as_uint(As[buf][kb + tig][mb + gid]);
                af[mf][1] = __float_as_uint(As[buf][kb + tig][mb + gid + 8]);
                af[mf][2] = __float_as_uint(As[buf][kb + tig + 4][mb + gid]);
                af[mf][3] = __float_as_uint(As[buf][kb + tig + 4][mb + gid + 8]);
            }
#pragma unroll
            for (int nf = 0; nf < 4; nf++) {
                int nb = wn + nf * 8;
                bf[nf][0] = __float_as_uint(Bs[buf][kb + tig][nb + gid]);
                bf[nf][1] = __float_as_uint(Bs[buf][kb + tig + 4][nb + gid]);
            }
#pragma unroll
            for (int mf = 0; mf < 4; mf++)
#pragma unroll
                for (int nf = 0; nf < 4; nf++)
                    mma_tf32(acc[mf][nf], af[mf], bf[nf]);
        }
    };

    load_tile(0);
    store_tile(0);
    __syncthreads();

    for (int kt = 0; kt < KT; kt++) {
        int cur = kt & 1;
        bool has = (kt + 1 < KT);
        if (has) load_tile(kt + 1);
        compute(cur);
        if (has) store_tile(1 - cur);
        __syncthreads();
    }

    // ---- epilogue ----
#pragma unroll
    for (int mf = 0; mf < 4; mf++) {
#pragma unroll
        for (int nf = 0; nf < 4; nf++) {
            int r = bm0 + wm + mf * 16 + gid;
            int c = bn0 + wn + nf * 8 + tig * 2;
            float2 v0 = make_float2(acc[mf][nf][0], acc[mf][nf][1]);
            float2 v1 = make_float2(acc[mf][nf][2], acc[mf][nf][3]);
            *(float2*)(Cm + (size_t)r * ncols + c) = v0;
            *(float2*)(Cm + (size_t)(r + 8) * ncols + c) = v1;
        }
    }
}

// ---------------- launcher ----------------
extern "C" void kernel_launch(void* const* d_in, const int* in_sizes, int n_in,
                              void* d_out, int out_size) {
    (void)in_sizes; (void)n_in; (void)out_size;
    const float* x      = (const float*)d_in[0];
    const float* w_qkv  = (const float*)d_in[1];
    const float* w_proj = (const float*)d_in[2];
    const float* g_in   = (const float*)d_in[3];
    const float* b_in   = (const float*)d_in[4];
    const float* g_out  = (const float*)d_in[5];
    const float* b_out  = (const float*)d_in[6];
    float* out = (float*)d_out;

    float *qkv, *mu, *rstd, *invnk, *invnq, *mu2, *rstd2, *kv;
    cudaGetSymbolAddress((void**)&qkv,   g_qkv);
    cudaGetSymbolAddress((void**)&mu,    g_mu);
    cudaGetSymbolAddress((void**)&rstd,  g_rstd);
    cudaGetSymbolAddress((void**)&invnk, g_invnk);
    cudaGetSymbolAddress((void**)&invnq, g_invnq);
    cudaGetSymbolAddress((void**)&mu2,   g_mu2);
    cudaGetSymbolAddress((void**)&rstd2, g_rstd2);
    cudaGetSymbolAddress((void**)&kv,    g_kv);

    // K1: LN-in stats
    ln_stats_kernel<<<MTOK / 8, 256>>>(x, mu, rstd);

    // K2: qkv = LN(x) @ w_qkv   (M=32768, N=2304, K=768)
    gemm_tf32_kernel<0><<<dim3(QKVCOLS / BN, MTOK / BM), 256>>>(
        x, CDIM, w_qkv, QKVCOLS, qkv, g_in, b_in, mu, rstd, nullptr, nullptr);

    // K3a: per-token 1/||k||
    knorm_kernel<<<MTOK / 8, 256>>>(qkv, invnk);

    // K3b: kv[b] = sum_n phi_k * v
    zero_kv_kernel<<<BATCH, EDIM>>>(kv);
    kv_acc_kernel<<<dim3(SEQ / 128, BATCH), 256>>>(qkv, invnk, kv);

    // K4: output-LN stats from q and kv (attn never materialized)
    qstats_kernel<<<MTOK / 8, 256>>>(qkv, kv, invnq, mu2, rstd2);

    // K5: out = LN(phi_q * kv) @ w_proj   (M=32768, N=768, K=768)
    gemm_tf32_kernel<1><<<dim3(CDIM / BN, MTOK / BM), 256>>>(
        qkv, QKVCOLS, w_proj, CDIM, out, g_out, b_out, invnq, mu2, rstd2, kv);
}

// round 4
// speedup vs baseline: 1.1111x; 1.1111x over previous
#include <cuda_runtime.h>
#include <cstdint>
#include <cstddef>

// Shapes
#define BATCH   8
#define SEQ     4096
#define CDIM    768
#define EDIM    768
#define MTOK    (BATCH*SEQ)      // 32768
#define QKVCOLS (3*EDIM)         // 2304

// ---------------- scratch ----------------
__device__ float g_qkv[(size_t)MTOK * QKVCOLS];      // 302 MB (tf32-rounded)
__device__ float g_xr[(size_t)MTOK * CDIM];          // 96 MB tf32-rounded x
__device__ float g_wgt[(size_t)QKVCOLS * CDIM];      // WgT[n][k] 7 MB
__device__ float g_wbt[(size_t)BATCH * EDIM * EDIM]; // WbT[b][n][e] 19 MB
__device__ float g_s1[QKVCOLS];
__device__ float g_s2[QKVCOLS];
__device__ float g_t1[CDIM];
__device__ float g_t2[CDIM];
__device__ float g_alpha1[MTOK];
__device__ float g_beta1[MTOK];
__device__ float g_alpha2[MTOK];
__device__ float g_beta2[MTOK];
__device__ float g_invnk[MTOK];
__device__ float g_kv[BATCH * EDIM];

// ---------------- helpers ----------------
__device__ __forceinline__ float wsum(float v) {
#pragma unroll
    for (int o = 16; o > 0; o >>= 1) v += __shfl_xor_sync(0xFFFFFFFFu, v, o);
    return v;
}
__device__ __forceinline__ float tf32f(float x) {
    uint32_t u;
    asm("cvt.rna.tf32.f32 %0, %1;" : "=r"(u) : "f"(x));
    return __uint_as_float(u);
}
__device__ __forceinline__ uint32_t smem_u32(const void* p) {
    uint32_t a;
    asm("{ .reg .u64 t; cvta.to.shared.u64 t, %1; cvt.u32.u64 %0, t; }" : "=r"(a) : "l"(p));
    return a;
}
__device__ __forceinline__ void cpasync16(uint32_t s, const void* g) {
    asm volatile("cp.async.cg.shared.global [%0], [%1], 16;" :: "r"(s), "l"(g));
}
__device__ __forceinline__ void cp_commit() {
    asm volatile("cp.async.commit_group;" ::: "memory");
}
__device__ __forceinline__ void cp_wait1() {
    asm volatile("cp.async.wait_group 1;" ::: "memory");
}
__device__ __forceinline__ void mma_tf32(float* c, const uint32_t* a, const uint32_t* b) {
    asm volatile(
        "mma.sync.aligned.m16n8k8.row.col.f32.tf32.tf32.f32 "
        "{%0,%1,%2,%3}, {%4,%5,%6,%7}, {%8,%9}, {%0,%1,%2,%3};"
        : "+f"(c[0]), "+f"(c[1]), "+f"(c[2]), "+f"(c[3])
        : "r"(a[0]), "r"(a[1]), "r"(a[2]), "r"(a[3]), "r"(b[0]), "r"(b[1]));
}

// ---------------- mma.sync tf32 GEMM, 3-stage cp.async pipeline ----------------
// A: [M x CDIM] row-major tf32-rounded.  B: rows of CDIM contiguous ([n][k]), tf32-rounded.
// C[m][n] = alpha[m]*acc + beta[m]*p1[n] + p2[n]   (optionally tf32-rounded)
#define BM 128
#define BN 128
#define BK 32
#define LDT (BK + 4)            // 36 floats: conflict-free fragment LDS
#define STAGES 3
#define KTILES (CDIM / BK)      // 24
#define GEMM_SMEM (STAGES * (BM + BN) * LDT * 4)   // 110592 B

template <int ROUND>
__global__ void __launch_bounds__(256, 2)
gemm_mma_kernel(const float* __restrict__ A, int lda,
                const float* __restrict__ Bw, size_t bstride,
                float* __restrict__ C, int ldc,
                const float* __restrict__ alpha, const float* __restrict__ beta,
                const float* __restrict__ p1, const float* __restrict__ p2) {
    extern __shared__ float smem[];
    float* As = smem;                                // [STAGES][BM][LDT]
    float* Bs = smem + STAGES * BM * LDT;            // [STAGES][BN][LDT]

    const int tid = threadIdx.x, lane = tid & 31, wid = tid >> 5;
    const int gid = lane >> 2, tig = lane & 3;
    const int wm = (wid >> 2) * 64, wn = (wid & 3) * 32;
    const int bm0 = blockIdx.y * BM, bn0 = blockIdx.x * BN;

    // loader mapping: thread -> (row = tid/2, float col base = (tid&1)*16), 4 chunks of 16B
    const int lrow = tid >> 1, lcol = (tid & 1) * 16;
    const float* Ag = A + (size_t)(bm0 + lrow) * lda + lcol;
    const float* Bg = Bw + (size_t)(bm0 >> 12) * bstride + (size_t)(bn0 + lrow) * CDIM + lcol;
    const uint32_t aS0 = smem_u32(As) + (uint32_t)(lrow * LDT + lcol) * 4;
    const uint32_t bS0 = smem_u32(Bs) + (uint32_t)(lrow * LDT + lcol) * 4;

    float acc[4][4][4];
#pragma unroll
    for (int i = 0; i < 4; i++)
#pragma unroll
        for (int j = 0; j < 4; j++)
#pragma unroll
            for (int r = 0; r < 4; r++) acc[i][j][r] = 0.f;

    auto load_stage = [&](int s, int kt) {
        const float* ag = Ag + kt * BK;
        const float* bg = Bg + kt * BK;
        uint32_t ad = aS0 + (uint32_t)(s * BM * LDT) * 4;
        uint32_t bd = bS0 + (uint32_t)(s * BN * LDT) * 4;
#pragma unroll
        for (int j = 0; j < 4; j++) cpasync16(ad + j * 16, ag + j * 4);
#pragma unroll
        for (int j = 0; j < 4; j++) cpasync16(bd + j * 16, bg + j * 4);
    };

    auto compute = [&](int s) {
        const float* Asl = As + s * BM * LDT;
        const float* Bsl = Bs + s * BN * LDT;
#pragma unroll
        for (int ks = 0; ks < 4; ks++) {
            const int kb = ks * 8;
            uint32_t af[4][4], bf[4][2];
#pragma unroll
            for (int mf = 0; mf < 4; mf++) {
                const float* pa = Asl + (wm + mf * 16 + gid) * LDT + kb + tig;
                af[mf][0] = __float_as_uint(pa[0]);
                af[mf][1] = __float_as_uint(pa[8 * LDT]);
                af[mf][2] = __float_as_uint(pa[4]);
                af[mf][3] = __float_as_uint(pa[8 * LDT + 4]);
            }
#pragma unroll
            for (int nf = 0; nf < 4; nf++) {
                const float* pb = Bsl + (wn + nf * 8 + gid) * LDT + kb + tig;
                bf[nf][0] = __float_as_uint(pb[0]);
                bf[nf][1] = __float_as_uint(pb[4]);
            }
#pragma unroll
            for (int mf = 0; mf < 4; mf++)
#pragma unroll
                for (int nf = 0; nf < 4; nf++)
                    mma_tf32(acc[mf][nf], af[mf], bf[nf]);
        }
    };

    load_stage(0, 0); cp_commit();
    load_stage(1, 1); cp_commit();
    cp_wait1();
    __syncthreads();

    for (int kt = 0; kt < KTILES; kt++) {
        int s = kt % STAGES;
        if (kt + 2 < KTILES) load_stage((kt + 2) % STAGES, kt + 2);
        cp_commit();
        compute(s);
        cp_wait1();
        __syncthreads();
    }

    // epilogue
#pragma unroll
    for (int mf = 0; mf < 4; mf++) {
        int r0 = bm0 + wm + mf * 16 + gid;
        float al0 = __ldg(alpha + r0), be0 = __ldg(beta + r0);
        float al1 = __ldg(alpha + r0 + 8), be1 = __ldg(beta + r0 + 8);
        float* crow0 = C + (size_t)r0 * ldc;
        float* crow1 = C + (size_t)(r0 + 8) * ldc;
#pragma unroll
        for (int nf = 0; nf < 4; nf++) {
            int c = bn0 + wn + nf * 8 + tig * 2;
            float q10 = __ldg(p1 + c), q11 = __ldg(p1 + c + 1);
            float q20 = __ldg(p2 + c), q21 = __ldg(p2 + c + 1);
            float v0 = al0 * acc[mf][nf][0] + be0 * q10 + q20;
            float v1 = al0 * acc[mf][nf][1] + be0 * q11 + q21;
            float v2 = al1 * acc[mf][nf][2] + be1 * q10 + q20;
            float v3 = al1 * acc[mf][nf][3] + be1 * q11 + q21;
            if (ROUND) { v0 = tf32f(v0); v1 = tf32f(v1); v2 = tf32f(v2); v3 = tf32f(v3); }
            *(float2*)(crow0 + c) = make_float2(v0, v1);
            *(float2*)(crow1 + c) = make_float2(v2, v3);
        }
    }
}

// ---------------- prep kernels ----------------
__global__ void roundx_kernel(const float* __restrict__ x, float* __restrict__ xr) {
    size_t i = (size_t)blockIdx.x * blockDim.x + threadIdx.x;
    float4 v = ((const float4*)x)[i];
    ((float4*)xr)[i] = make_float4(tf32f(v.x), tf32f(v.y), tf32f(v.z), tf32f(v.w));
}

__global__ void wqkvT_kernel(const float* __restrict__ w, const float* __restrict__ g,
                             float* __restrict__ wt) {
    __shared__ float t[32][33];
    int nb = blockIdx.x * 32, kb = blockIdx.y * 32;
    int tx = threadIdx.x, ty = threadIdx.y;
#pragma unroll
    for (int i = 0; i < 4; i++) {
        int k = kb + ty + i * 8;
        t[ty + i * 8][tx] = g[k] * w[(size_t)k * QKVCOLS + nb + tx];
    }
    __syncthreads();
#pragma unroll
    for (int i = 0; i < 4; i++) {
        int n = nb + ty + i * 8;
        wt[(size_t)n * CDIM + kb + tx] = tf32f(t[tx][ty + i * 8]);
    }
}

__global__ void colsum1_kernel(const float* __restrict__ w, const float* __restrict__ g,
                               const float* __restrict__ b, float* __restrict__ s1,
                               float* __restrict__ s2) {
    int n = blockIdx.x * 256 + threadIdx.x;
    float a = 0.f, c = 0.f;
    for (int k = 0; k < CDIM; k++) {
        float wv = w[(size_t)k * QKVCOLS + n];
        a += g[k] * wv; c += b[k] * wv;
    }
    s1[n] = a; s2[n] = c;
}

__global__ void wprojT_kernel(const float* __restrict__ wp, const float* __restrict__ g2,
                              const float* __restrict__ kv, float* __restrict__ wbt) {
    __shared__ float t[32][33];
    int nb = blockIdx.x * 32, eb = blockIdx.y * 32, b = blockIdx.z;
    int tx = threadIdx.x, ty = threadIdx.y;
#pragma unroll
    for (int i = 0; i < 4; i++) {
        int e = eb + ty + i * 8;
        t[ty + i * 8][tx] = kv[b * EDIM + e] * g2[e] * wp[(size_t)e * CDIM + nb + tx];
    }
    __syncthreads();
#pragma unroll
    for (int i = 0; i < 4; i++) {
        int n = nb + ty + i * 8;
        wbt[((size_t)b * EDIM + n) * EDIM + eb + tx] = tf32f(t[tx][ty + i * 8]);
    }
}

__global__ void colsum2_kernel(const float* __restrict__ wp, const float* __restrict__ g2,
                               const float* __restrict__ b2, float* __restrict__ t1,
                               float* __restrict__ t2) {
    int n = blockIdx.x * 256 + threadIdx.x;
    float a = 0.f, c = 0.f;
    for (int e = 0; e < EDIM; e++) {
        float wv = wp[(size_t)e * CDIM + n];
        a += g2[e] * wv; c += b2[e] * wv;
    }
    t1[n] = a; t2[n] = c;
}

// ---------------- stats kernels ----------------
__global__ void ln_stats_kernel(const float* __restrict__ x,
                                float* __restrict__ alpha, float* __restrict__ beta) {
    int m = blockIdx.x * 8 + (threadIdx.x >> 5);
    int lane = threadIdx.x & 31;
    const float* row = x + (size_t)m * CDIM;
    float v[24], s = 0.f;
#pragma unroll
    for (int i = 0; i < 24; i++) { v[i] = row[lane + 32 * i]; s += v[i]; }
    s = wsum(s);
    float mean = s * (1.0f / CDIM);
    float ss = 0.f;
#pragma unroll
    for (int i = 0; i < 24; i++) { float d = v[i] - mean; ss += d * d; }
    ss = wsum(ss);
    if (lane == 0) {
        float rs = rsqrtf(ss * (1.0f / CDIM) + 1e-5f);
        alpha[m] = rs;
        beta[m] = -mean * rs;
    }
}

__global__ void knorm_kernel(const float* __restrict__ qkv, float* __restrict__ invnk) {
    int m = blockIdx.x * 8 + (threadIdx.x >> 5);
    int lane = threadIdx.x & 31;
    const float* row = qkv + (size_t)m * QKVCOLS + EDIM;
    float ss = 0.f;
#pragma unroll
    for (int i = 0; i < 24; i++) { float t = row[lane + 32 * i]; ss += t * t; }
    ss = wsum(ss);
    if (lane == 0) invnk[m] = 1.0f / fmaxf(sqrtf(ss), 1e-12f);
}

__global__ void zero_kv_kernel(float* __restrict__ kv) {
    kv[blockIdx.x * EDIM + threadIdx.x] = 0.f;
}

__global__ void kv_acc_kernel(const float* __restrict__ qkv,
                              const float* __restrict__ invnk,
                              float* __restrict__ kv) {
    int b = blockIdx.y, chunk = blockIdx.x, tid = threadIdx.x;
    float a0 = 0.f, a1 = 0.f, a2 = 0.f;
    int m0 = b * SEQ + chunk * 128;
    for (int t = 0; t < 128; t++) {
        size_t base = (size_t)(m0 + t) * QKVCOLS;
        float inv = __ldg(invnk + m0 + t);
        const float* kr = qkv + base + EDIM;
        const float* vr = qkv + base + 2 * EDIM;
        a0 += kr[tid] * inv * vr[tid];
        a1 += kr[tid + 256] * inv * vr[tid + 256];
        a2 += kr[tid + 512] * inv * vr[tid + 512];
    }
    atomicAdd(&kv[b * EDIM + tid], a0);
    atomicAdd(&kv[b * EDIM + tid + 256], a1);
    atomicAdd(&kv[b * EDIM + tid + 512], a2);
}

__global__ void qstats_kernel(const float* __restrict__ qkv, const float* __restrict__ kv,
                              float* __restrict__ alpha, float* __restrict__ beta) {
    int m = blockIdx.x * 8 + (threadIdx.x >> 5);
    int lane = threadIdx.x & 31;
    const float* qr = qkv + (size_t)m * QKVCOLS;
    const float* kvr = kv + (m >> 12) * EDIM;
    float sq = 0.f, s1 = 0.f, s2 = 0.f;
#pragma unroll
    for (int i = 0; i < 24; i++) {
        int e = lane + 32 * i;
        float q = qr[e], c = kvr[e];
        sq += q * q;
        float a = q * c;
        s1 += a; s2 += a * a;
    }
    sq = wsum(sq); s1 = wsum(s1); s2 = wsum(s2);
    if (lane == 0) {
        float inv = 1.0f / fmaxf(sqrtf(sq), 1e-12f);
        float mean = s1 * inv * (1.0f / EDIM);
        float msq = s2 * inv * inv * (1.0f / EDIM);
        float var = fmaxf(msq - mean * mean, 0.f);
        float rs2 = rsqrtf(var + 1e-5f);
        alpha[m] = rs2 * inv;
        beta[m] = -mean * rs2;
    }
}

// ---------------- launcher ----------------
extern "C" void kernel_launch(void* const* d_in, const int* in_sizes, int n_in,
                              void* d_out, int out_size) {
    (void)in_sizes; (void)n_in; (void)out_size;
    const float* x      = (const float*)d_in[0];
    const float* w_qkv  = (const float*)d_in[1];
    const float* w_proj = (const float*)d_in[2];
    const float* g_in   = (const float*)d_in[3];
    const float* b_in   = (const float*)d_in[4];
    const float* g_out  = (const float*)d_in[5];
    const float* b_out  = (const float*)d_in[6];
    float* out = (float*)d_out;

    float *qkv, *xr, *wgt, *wbt, *s1, *s2, *t1, *t2, *a1, *be1, *a2, *be2, *invnk, *kv;
    cudaGetSymbolAddress((void**)&qkv, g_qkv);
    cudaGetSymbolAddress((void**)&xr, g_xr);
    cudaGetSymbolAddress((void**)&wgt, g_wgt);
    cudaGetSymbolAddress((void**)&wbt, g_wbt);
    cudaGetSymbolAddress((void**)&s1, g_s1);
    cudaGetSymbolAddress((void**)&s2, g_s2);
    cudaGetSymbolAddress((void**)&t1, g_t1);
    cudaGetSymbolAddress((void**)&t2, g_t2);
    cudaGetSymbolAddress((void**)&a1, g_alpha1);
    cudaGetSymbolAddress((void**)&be1, g_beta1);
    cudaGetSymbolAddress((void**)&a2, g_alpha2);
    cudaGetSymbolAddress((void**)&be2, g_beta2);
    cudaGetSymbolAddress((void**)&invnk, g_invnk);
    cudaGetSymbolAddress((void**)&kv, g_kv);

    cudaFuncSetAttribute(gemm_mma_kernel<1>, cudaFuncAttributeMaxDynamicSharedMemorySize, GEMM_SMEM);
    cudaFuncSetAttribute(gemm_mma_kernel<0>, cudaFuncAttributeMaxDynamicSharedMemorySize, GEMM_SMEM);

    // prep
    roundx_kernel<<<(MTOK * CDIM / 4) / 256, 256>>>(x, xr);
    wqkvT_kernel<<<dim3(QKVCOLS / 32, CDIM / 32), dim3(32, 8)>>>(w_qkv, g_in, wgt);
    colsum1_kernel<<<QKVCOLS / 256, 256>>>(w_qkv, g_in, b_in, s1, s2);
    ln_stats_kernel<<<MTOK / 8, 256>>>(x, a1, be1);

    // GEMM1: qkv = xr @ WgT^T, LN affine epilogue, tf32-rounded output
    gemm_mma_kernel<1><<<dim3(QKVCOLS / BN, MTOK / BM), 256, GEMM_SMEM>>>(
        xr, CDIM, wgt, 0, qkv, QKVCOLS, a1, be1, s1, s2);

    // kv pipeline
    knorm_kernel<<<MTOK / 8, 256>>>(qkv, invnk);
    zero_kv_kernel<<<BATCH, EDIM>>>(kv);
    kv_acc_kernel<<<dim3(SEQ / 128, BATCH), 256>>>(qkv, invnk, kv);
    qstats_kernel<<<MTOK / 8, 256>>>(qkv, kv, a2, be2);

    // GEMM2 weights (need kv)
    wprojT_kernel<<<dim3(CDIM / 32, EDIM / 32, BATCH), dim3(32, 8)>>>(w_proj, g_out, kv, wbt);
    colsum2_kernel<<<CDIM / 256, 256>>>(w_proj, g_out, b_out, t1, t2);

    // GEMM2: out = q @ WbT^T, output-LN affine epilogue
    gemm_mma_kernel<0><<<dim3(CDIM / BN, MTOK / BM), 256, GEMM_SMEM>>>(
        qkv, QKVCOLS, wbt, (size_t)EDIM * EDIM, out, CDIM, a2, be2, t1, t2);
}

// round 7
// speedup vs baseline: 1.2107x; 1.0897x over previous
#include <cuda_runtime.h>
#include <cstdint>
#include <cstddef>

// Shapes
#define BATCH   8
#define SEQ     4096
#define CDIM    768
#define EDIM    768
#define MTOK    (BATCH*SEQ)      // 32768
#define QKVCOLS (3*EDIM)         // 2304

// ---------------- scratch ----------------
__device__ float g_qkv[(size_t)MTOK * QKVCOLS];      // 302 MB (tf32-rounded)
__device__ float g_xr[(size_t)MTOK * CDIM];          // 96 MB tf32-rounded x
__device__ float g_wgt[(size_t)QKVCOLS * CDIM];      // WgT[n][k] 7 MB
__device__ float g_wbt[(size_t)BATCH * EDIM * EDIM]; // WbT[b][n][e] 19 MB
__device__ float g_s1[QKVCOLS];
__device__ float g_s2[QKVCOLS];
__device__ float g_t1[CDIM];
__device__ float g_t2[CDIM];
__device__ float g_alpha1[MTOK];
__device__ float g_beta1[MTOK];
__device__ float g_alpha2[MTOK];
__device__ float g_beta2[MTOK];
__device__ float g_invnk[MTOK];
__device__ float g_kv[BATCH * EDIM];

// ---------------- helpers ----------------
__device__ __forceinline__ float wsum(float v) {
#pragma unroll
    for (int o = 16; o > 0; o >>= 1) v += __shfl_xor_sync(0xFFFFFFFFu, v, o);
    return v;
}
__device__ __forceinline__ float tf32f(float x) {
    uint32_t u;
    asm("cvt.rna.tf32.f32 %0, %1;" : "=r"(u) : "f"(x));
    return __uint_as_float(u);
}
__device__ __forceinline__ uint32_t smem_u32(const void* p) {
    uint32_t a;
    asm("{ .reg .u64 t; cvta.to.shared.u64 t, %1; cvt.u32.u64 %0, t; }" : "=r"(a) : "l"(p));
    return a;
}
__device__ __forceinline__ void cpasync16(uint32_t s, const void* g) {
    asm volatile("cp.async.cg.shared.global [%0], [%1], 16;" :: "r"(s), "l"(g));
}
__device__ __forceinline__ void cp_commit() {
    asm volatile("cp.async.commit_group;" ::: "memory");
}
__device__ __forceinline__ void cp_wait1() {
    asm volatile("cp.async.wait_group 1;" ::: "memory");
}
__device__ __forceinline__ void ldsm4(uint32_t* r, uint32_t addr) {
    asm volatile("ldmatrix.sync.aligned.m8n8.x4.shared.b16 {%0,%1,%2,%3}, [%4];"
        : "=r"(r[0]), "=r"(r[1]), "=r"(r[2]), "=r"(r[3]) : "r"(addr));
}
__device__ __forceinline__ void mma_tf32(float* c, const uint32_t* a, const uint32_t* b) {
    asm volatile(
        "mma.sync.aligned.m16n8k8.row.col.f32.tf32.tf32.f32 "
        "{%0,%1,%2,%3}, {%4,%5,%6,%7}, {%8,%9}, {%0,%1,%2,%3};"
        : "+f"(c[0]), "+f"(c[1]), "+f"(c[2]), "+f"(c[3])
        : "r"(a[0]), "r"(a[1]), "r"(a[2]), "r"(a[3]), "r"(b[0]), "r"(b[1]));
}

// ---------------- mma.sync tf32 GEMM, 3-stage cp.async + ldmatrix ----------------
// A: [M x CDIM] row-major tf32-rounded.  B: rows of CDIM contiguous ([n][k]), tf32-rounded.
// C[m][n] = alpha[m]*acc + beta[m]*p1[n] + p2[n]   (optionally tf32-rounded)
#define BM 128
#define BN 256
#define BK 32
#define LDT (BK + 4)            // 36 floats: ldmatrix phases hit all 32 banks
#define STAGES 3
#define KTILES (CDIM / BK)      // 24
#define GTHR 512
#define GEMM_SMEM (STAGES * (BM + BN) * LDT * 4)   // 165888 B

template <int ROUND>
__global__ void __launch_bounds__(GTHR, 1)
gemm_mma_kernel(const float* __restrict__ A, int lda,
                const float* __restrict__ Bw, size_t bstride,
                float* __restrict__ C, int ldc,
                const float* __restrict__ alpha, const float* __restrict__ beta,
                const float* __restrict__ p1, const float* __restrict__ p2) {
    extern __shared__ float smem[];
    float* As = smem;                                // [STAGES][BM][LDT]
    float* Bs = smem + STAGES * BM * LDT;            // [STAGES][BN][LDT]

    const int tid = threadIdx.x, lane = tid & 31, wid = tid >> 5;
    const int gid = lane >> 2, tig = lane & 3;
    const int wm = (wid >> 2) * 32;       // 4 warps in M -> 32 rows each
    const int wn = (wid & 3) * 64;        // 4 warps in N -> 64 cols each
    const int bm0 = blockIdx.y * BM, bn0 = blockIdx.x * BN;

    // ---- loader mapping ----
    const int arow = tid >> 2, acol = (tid & 3) * 8;
    const int brow = tid >> 1, bcol = (tid & 1) * 16;
    const float* Ag = A + (size_t)(bm0 + arow) * lda + acol;
    const float* Bg = Bw + (size_t)(bm0 >> 12) * bstride + (size_t)(bn0 + brow) * CDIM + bcol;
    const uint32_t aS0 = smem_u32(As) + (uint32_t)(arow * LDT + acol) * 4;
    const uint32_t bS0 = smem_u32(Bs) + (uint32_t)(brow * LDT + bcol) * 4;

    // ---- ldmatrix per-lane addresses (byte offsets within a stage) ----
    const int mi = lane >> 3, mr = lane & 7;
    uint32_t aLd[2];
#pragma unroll
    for (int mf = 0; mf < 2; mf++)
        aLd[mf] = (uint32_t)(((wm + mf * 16 + (mi & 1) * 8 + mr) * LDT + (mi >> 1) * 4) * 4);
    uint32_t bLd[4];
#pragma unroll
    for (int p = 0; p < 4; p++)
        bLd[p] = (uint32_t)(((wn + p * 16 + (mi >> 1) * 8 + mr) * LDT + (mi & 1) * 4) * 4);
    const uint32_t aBase = smem_u32(As), bBase = smem_u32(Bs);

    float acc[2][8][4];
#pragma unroll
    for (int i = 0; i < 2; i++)
#pragma unroll
        for (int j = 0; j < 8; j++)
#pragma unroll
            for (int r = 0; r < 4; r++) acc[i][j][r] = 0.f;

    auto load_stage = [&](int s, int kt) {
        const float* ag = Ag + kt * BK;
        const float* bg = Bg + kt * BK;
        uint32_t ad = aS0 + (uint32_t)(s * BM * LDT) * 4;
        uint32_t bd = bS0 + (uint32_t)(s * BN * LDT) * 4;
#pragma unroll
        for (int j = 0; j < 2; j++) cpasync16(ad + j * 16, ag + j * 4);
#pragma unroll
        for (int j = 0; j < 4; j++) cpasync16(bd + j * 16, bg + j * 4);
    };

    auto compute = [&](int s) {
        const uint32_t aSt = aBase + (uint32_t)(s * BM * LDT) * 4;
        const uint32_t bSt = bBase + (uint32_t)(s * BN * LDT) * 4;
#pragma unroll
        for (int ks = 0; ks < 4; ks++) {
            const uint32_t ko = (uint32_t)(ks * 8 * 4);   // 8 floats per k-step
            uint32_t af[2][4], bf[8][2];
#pragma unroll
            for (int mf = 0; mf < 2; mf++)
                ldsm4(af[mf], aSt + aLd[mf] + ko);
#pragma unroll
            for (int p = 0; p < 4; p++) {
                uint32_t r[4];
                ldsm4(r, bSt + bLd[p] + ko);
                bf[2 * p][0] = r[0]; bf[2 * p][1] = r[1];
                bf[2 * p + 1][0] = r[2]; bf[2 * p + 1][1] = r[3];
            }
#pragma unroll
            for (int mf = 0; mf < 2; mf++)
#pragma unroll
                for (int nf = 0; nf < 8; nf++)
                    mma_tf32(acc[mf][nf], af[mf], bf[nf]);
        }
    };

    load_stage(0, 0); cp_commit();
    load_stage(1, 1); cp_commit();
    cp_wait1();
    __syncthreads();

    for (int kt = 0; kt < KTILES; kt++) {
        int s = kt % STAGES;
        if (kt + 2 < KTILES) load_stage((kt + 2) % STAGES, kt + 2);
        cp_commit();
        compute(s);
        cp_wait1();
        __syncthreads();
    }

    // ---- epilogue ----
#pragma unroll
    for (int mf = 0; mf < 2; mf++) {
        int r0 = bm0 + wm + mf * 16 + gid;
        float al0 = __ldg(alpha + r0), be0 = __ldg(beta + r0);
        float al1 = __ldg(alpha + r0 + 8), be1 = __ldg(beta + r0 + 8);
        float* crow0 = C + (size_t)r0 * ldc;
        float* crow1 = C + (size_t)(r0 + 8) * ldc;
#pragma unroll
        for (int nf = 0; nf < 8; nf++) {
            int c = bn0 + wn + nf * 8 + tig * 2;
            float q10 = __ldg(p1 + c), q11 = __ldg(p1 + c + 1);
            float q20 = __ldg(p2 + c), q21 = __ldg(p2 + c + 1);
            float v0 = al0 * acc[mf][nf][0] + be0 * q10 + q20;
            float v1 = al0 * acc[mf][nf][1] + be0 * q11 + q21;
            float v2 = al1 * acc[mf][nf][2] + be1 * q10 + q20;
            float v3 = al1 * acc[mf][nf][3] + be1 * q11 + q21;
            if (ROUND) { v0 = tf32f(v0); v1 = tf32f(v1); v2 = tf32f(v2); v3 = tf32f(v3); }
            *(float2*)(crow0 + c) = make_float2(v0, v1);
            *(float2*)(crow1 + c) = make_float2(v2, v3);
        }
    }
}

// ---------------- prep kernels ----------------
__global__ void roundx_kernel(const float* __restrict__ x, float* __restrict__ xr) {
    size_t i = (size_t)blockIdx.x * blockDim.x + threadIdx.x;
    float4 v = ((const float4*)x)[i];
    ((float4*)xr)[i] = make_float4(tf32f(v.x), tf32f(v.y), tf32f(v.z), tf32f(v.w));
}

__global__ void wqkvT_kernel(const float* __restrict__ w, const float* __restrict__ g,
                             float* __restrict__ wt) {
    __shared__ float t[32][33];
    int nb = blockIdx.x * 32, kb = blockIdx.y * 32;
    int tx = threadIdx.x, ty = threadIdx.y;
#pragma unroll
    for (int i = 0; i < 4; i++) {
        int k = kb + ty + i * 8;
        t[ty + i * 8][tx] = g[k] * w[(size_t)k * QKVCOLS + nb + tx];
    }
    __syncthreads();
#pragma unroll
    for (int i = 0; i < 4; i++) {
        int n = nb + ty + i * 8;
        wt[(size_t)n * CDIM + kb + tx] = tf32f(t[tx][ty + i * 8]);
    }
}

__global__ void colsum1_kernel(const float* __restrict__ w, const float* __restrict__ g,
                               const float* __restrict__ b, float* __restrict__ s1,
                               float* __restrict__ s2) {
    int n = blockIdx.x * 256 + threadIdx.x;
    float a = 0.f, c = 0.f;
    for (int k = 0; k < CDIM; k++) {
        float wv = w[(size_t)k * QKVCOLS + n];
        a += g[k] * wv; c += b[k] * wv;
    }
    s1[n] = a; s2[n] = c;
}

__global__ void wprojT_kernel(const float* __restrict__ wp, const float* __restrict__ g2,
                              const float* __restrict__ kv, float* __restrict__ wbt) {
    __shared__ float t[32][33];
    int nb = blockIdx.x * 32, eb = blockIdx.y * 32, b = blockIdx.z;
    int tx = threadIdx.x, ty = threadIdx.y;
#pragma unroll
    for (int i = 0; i < 4; i++) {
        int e = eb + ty + i * 8;
        t[ty + i * 8][tx] = kv[b * EDIM + e] * g2[e] * wp[(size_t)e * CDIM + nb + tx];
    }
    __syncthreads();
#pragma unroll
    for (int i = 0; i < 4; i++) {
        int n = nb + ty + i * 8;
        wbt[((size_t)b * EDIM + n) * EDIM + eb + tx] = tf32f(t[tx][ty + i * 8]);
    }
}

__global__ void colsum2_kernel(const float* __restrict__ wp, const float* __restrict__ g2,
                               const float* __restrict__ b2, float* __restrict__ t1,
                               float* __restrict__ t2) {
    int n = blockIdx.x * 256 + threadIdx.x;
    float a = 0.f, c = 0.f;
    for (int e = 0; e < EDIM; e++) {
        float wv = wp[(size_t)e * CDIM + n];
        a += g2[e] * wv; c += b2[e] * wv;
    }
    t1[n] = a; t2[n] = c;
}

// ---------------- stats kernels ----------------
__global__ void ln_stats_kernel(const float* __restrict__ x,
                                float* __restrict__ alpha, float* __restrict__ beta) {
    int m = blockIdx.x * 8 + (threadIdx.x >> 5);
    int lane = threadIdx.x & 31;
    const float* row = x + (size_t)m * CDIM;
    float v[24], s = 0.f;
#pragma unroll
    for (int i = 0; i < 24; i++) { v[i] = row[lane + 32 * i]; s += v[i]; }
    s = wsum(s);
    float mean = s * (1.0f / CDIM);
    float ss = 0.f;
#pragma unroll
    for (int i = 0; i < 24; i++) { float d = v[i] - mean; ss += d * d; }
    ss = wsum(ss);
    if (lane == 0) {
        float rs = rsqrtf(ss * (1.0f / CDIM) + 1e-5f);
        alpha[m] = rs;
        beta[m] = -mean * rs;
    }
}

__global__ void knorm_kernel(const float* __restrict__ qkv, float* __restrict__ invnk) {
    int m = blockIdx.x * 8 + (threadIdx.x >> 5);
    int lane = threadIdx.x & 31;
    const float* row = qkv + (size_t)m * QKVCOLS + EDIM;
    float ss = 0.f;
#pragma unroll
    for (int i = 0; i < 24; i++) { float t = row[lane + 32 * i]; ss += t * t; }
    ss = wsum(ss);
    if (lane == 0) invnk[m] = 1.0f / fmaxf(sqrtf(ss), 1e-12f);
}

__global__ void zero_kv_kernel(float* __restrict__ kv) {
    kv[blockIdx.x * EDIM + threadIdx.x] = 0.f;
}

__global__ void kv_acc_kernel(const float* __restrict__ qkv,
                              const float* __restrict__ invnk,
                              float* __restrict__ kv) {
    int b = blockIdx.y, chunk = blockIdx.x, tid = threadIdx.x;
    float a0 = 0.f, a1 = 0.f, a2 = 0.f;
    int m0 = b * SEQ + chunk * 128;
    for (int t = 0; t < 128; t++) {
        size_t base = (size_t)(m0 + t) * QKVCOLS;
        float inv = __ldg(invnk + m0 + t);
        const float* kr = qkv + base + EDIM;
        const float* vr = qkv + base + 2 * EDIM;
        a0 += kr[tid] * inv * vr[tid];
        a1 += kr[tid + 256] * inv * vr[tid + 256];
        a2 += kr[tid + 512] * inv * vr[tid + 512];
    }
    atomicAdd(&kv[b * EDIM + tid], a0);
    atomicAdd(&kv[b * EDIM + tid + 256], a1);
    atomicAdd(&kv[b * EDIM + tid + 512], a2);
}

__global__ void qstats_kernel(const float* __restrict__ qkv, const float* __restrict__ kv,
                              float* __restrict__ alpha, float* __restrict__ beta) {
    int m = blockIdx.x * 8 + (threadIdx.x >> 5);
    int lane = threadIdx.x & 31;
    const float* qr = qkv + (size_t)m * QKVCOLS;
    const float* kvr = kv + (m >> 12) * EDIM;
    float sq = 0.f, s1 = 0.f, s2 = 0.f;
#pragma unroll
    for (int i = 0; i < 24; i++) {
        int e = lane + 32 * i;
        float q = qr[e], c = kvr[e];
        sq += q * q;
        float a = q * c;
        s1 += a; s2 += a * a;
    }
    sq = wsum(sq); s1 = wsum(s1); s2 = wsum(s2);
    if (lane == 0) {
        float inv = 1.0f / fmaxf(sqrtf(sq), 1e-12f);
        float mean = s1 * inv * (1.0f / EDIM);
        float msq = s2 * inv * inv * (1.0f / EDIM);
        float var = fmaxf(msq - mean * mean, 0.f);
        float rs2 = rsqrtf(var + 1e-5f);
        alpha[m] = rs2 * inv;
        beta[m] = -mean * rs2;
    }
}

// ---------------- launcher ----------------
extern "C" void kernel_launch(void* const* d_in, const int* in_sizes, int n_in,
                              void* d_out, int out_size) {
    (void)in_sizes; (void)n_in; (void)out_size;
    const float* x      = (const float*)d_in[0];
    const float* w_qkv  = (const float*)d_in[1];
    const float* w_proj = (const float*)d_in[2];
    const float* g_in   = (const float*)d_in[3];
    const float* b_in   = (const float*)d_in[4];
    const float* g_out  = (const float*)d_in[5];
    const float* b_out  = (const float*)d_in[6];
    float* out = (float*)d_out;

    float *qkv, *xr, *wgt, *wbt, *s1, *s2, *t1, *t2, *a1, *be1, *a2, *be2, *invnk, *kv;
    cudaGetSymbolAddress((void**)&qkv, g_qkv);
    cudaGetSymbolAddress((void**)&xr, g_xr);
    cudaGetSymbolAddress((void**)&wgt, g_wgt);
    cudaGetSymbolAddress((void**)&wbt, g_wbt);
    cudaGetSymbolAddress((void**)&s1, g_s1);
    cudaGetSymbolAddress((void**)&s2, g_s2);
    cudaGetSymbolAddress((void**)&t1, g_t1);
    cudaGetSymbolAddress((void**)&t2, g_t2);
    cudaGetSymbolAddress((void**)&a1, g_alpha1);
    cudaGetSymbolAddress((void**)&be1, g_beta1);
    cudaGetSymbolAddress((void**)&a2, g_alpha2);
    cudaGetSymbolAddress((void**)&be2, g_beta2);
    cudaGetSymbolAddress((void**)&invnk, g_invnk);
    cudaGetSymbolAddress((void**)&kv, g_kv);

    cudaFuncSetAttribute(gemm_mma_kernel<1>, cudaFuncAttributeMaxDynamicSharedMemorySize, GEMM_SMEM);
    cudaFuncSetAttribute(gemm_mma_kernel<0>, cudaFuncAttributeMaxDynamicSharedMemorySize, GEMM_SMEM);

    // prep
    roundx_kernel<<<(MTOK * CDIM / 4) / 256, 256>>>(x, xr);
    wqkvT_kernel<<<dim3(QKVCOLS / 32, CDIM / 32), dim3(32, 8)>>>(w_qkv, g_in, wgt);
    colsum1_kernel<<<QKVCOLS / 256, 256>>>(w_qkv, g_in, b_in, s1, s2);
    ln_stats_kernel<<<MTOK / 8, 256>>>(x, a1, be1);

    // GEMM1: qkv = xr @ WgT^T, LN affine epilogue, tf32-rounded output
    gemm_mma_kernel<1><<<dim3(QKVCOLS / BN, MTOK / BM), GTHR, GEMM_SMEM>>>(
        xr, CDIM, wgt, 0, qkv, QKVCOLS, a1, be1, s1, s2);

    // kv pipeline
    knorm_kernel<<<MTOK / 8, 256>>>(qkv, invnk);
    zero_kv_kernel<<<BATCH, EDIM>>>(kv);
    kv_acc_kernel<<<dim3(SEQ / 128, BATCH), 256>>>(qkv, invnk, kv);
    qstats_kernel<<<MTOK / 8, 256>>>(qkv, kv, a2, be2);

    // GEMM2 weights (need kv)
    wprojT_kernel<<<dim3(CDIM / 32, EDIM / 32, BATCH), dim3(32, 8)>>>(w_proj, g_out, kv, wbt);
    colsum2_kernel<<<CDIM / 256, 256>>>(w_proj, g_out, b_out, t1, t2);

    // GEMM2: out = q @ WbT^T, output-LN affine epilogue
    gemm_mma_kernel<0><<<dim3(CDIM / BN, MTOK / BM), GTHR, GEMM_SMEM>>>(
        qkv, QKVCOLS, wbt, (size_t)EDIM * EDIM, out, CDIM, a2, be2, t1, t2);
}

// round 8
// speedup vs baseline: 1.3223x; 1.0922x over previous
#include <cuda_runtime.h>
#include <cstdint>
#include <cstddef>

// Shapes
#define BATCH   8
#define SEQ     4096
#define CDIM    768
#define EDIM    768
#define MTOK    (BATCH*SEQ)      // 32768
#define QKVCOLS (3*EDIM)         // 2304

// ---------------- scratch ----------------
__device__ float g_qkv[(size_t)MTOK * QKVCOLS];      // 302 MB (tf32-rounded)
__device__ float g_xr[(size_t)MTOK * CDIM];          // 96 MB tf32-rounded x
__device__ float g_wgt[(size_t)QKVCOLS * CDIM];      // WgT[n][k] 7 MB
__device__ float g_wbt[(size_t)BATCH * EDIM * EDIM]; // WbT[b][n][e] 19 MB
__device__ float g_s1[QKVCOLS];
__device__ float g_s2[QKVCOLS];
__device__ float g_t1[CDIM];
__device__ float g_t2[CDIM];
__device__ float g_alpha1[MTOK];
__device__ float g_beta1[MTOK];
__device__ float g_alpha2[MTOK];
__device__ float g_beta2[MTOK];
__device__ float g_invnk[MTOK];
__device__ float g_kv[BATCH * EDIM];

// ---------------- helpers ----------------
__device__ __forceinline__ float wsum(float v) {
#pragma unroll
    for (int o = 16; o > 0; o >>= 1) v += __shfl_xor_sync(0xFFFFFFFFu, v, o);
    return v;
}
__device__ __forceinline__ float tf32f(float x) {
    uint32_t u;
    asm("cvt.rna.tf32.f32 %0, %1;" : "=r"(u) : "f"(x));
    return __uint_as_float(u);
}
__device__ __forceinline__ uint32_t smem_u32(const void* p) {
    uint32_t a;
    asm("{ .reg .u64 t; cvta.to.shared.u64 t, %1; cvt.u32.u64 %0, t; }" : "=r"(a) : "l"(p));
    return a;
}
__device__ __forceinline__ void cpasync16(uint32_t s, const void* g) {
    asm volatile("cp.async.cg.shared.global [%0], [%1], 16;" :: "r"(s), "l"(g));
}
__device__ __forceinline__ void cp_commit() {
    asm volatile("cp.async.commit_group;" ::: "memory");
}
__device__ __forceinline__ void cp_wait2() {
    asm volatile("cp.async.wait_group 2;" ::: "memory");
}
__device__ __forceinline__ void ldsm4(uint32_t* r, uint32_t addr) {
    asm volatile("ldmatrix.sync.aligned.m8n8.x4.shared.b16 {%0,%1,%2,%3}, [%4];"
        : "=r"(r[0]), "=r"(r[1]), "=r"(r[2]), "=r"(r[3]) : "r"(addr));
}
__device__ __forceinline__ void mma_tf32(float* c, const uint32_t* a, const uint32_t* b) {
    asm volatile(
        "mma.sync.aligned.m16n8k8.row.col.f32.tf32.tf32.f32 "
        "{%0,%1,%2,%3}, {%4,%5,%6,%7}, {%8,%9}, {%0,%1,%2,%3};"
        : "+f"(c[0]), "+f"(c[1]), "+f"(c[2]), "+f"(c[3])
        : "r"(a[0]), "r"(a[1]), "r"(a[2]), "r"(a[3]), "r"(b[0]), "r"(b[1]));
}

// ---------------- mma.sync tf32 GEMM, 4-stage cp.async + ldmatrix ----------------
#define BM 128
#define BN 256
#define BK 32
#define LDT (BK + 4)            // 36 floats
#define STAGES 4
#define KTILES (CDIM / BK)      // 24
#define GTHR 512
#define GEMM_SMEM (STAGES * (BM + BN) * LDT * 4)   // 221184 B

template <int ROUND>
__global__ void __launch_bounds__(GTHR, 1)
gemm_mma_kernel(const float* __restrict__ A, int lda,
                const float* __restrict__ Bw, size_t bstride,
                float* __restrict__ C, int ldc,
                const float* __restrict__ alpha, const float* __restrict__ beta,
                const float* __restrict__ p1, const float* __restrict__ p2) {
    extern __shared__ float smem[];
    float* As = smem;                                // [STAGES][BM][LDT]
    float* Bs = smem + STAGES * BM * LDT;            // [STAGES][BN][LDT]

    const int tid = threadIdx.x, lane = tid & 31, wid = tid >> 5;
    const int gid = lane >> 2, tig = lane & 3;
    const int wm = (wid >> 2) * 32;
    const int wn = (wid & 3) * 64;
    const int bm0 = blockIdx.y * BM, bn0 = blockIdx.x * BN;

    const int arow = tid >> 2, acol = (tid & 3) * 8;
    const int brow = tid >> 1, bcol = (tid & 1) * 16;
    const float* Ag = A + (size_t)(bm0 + arow) * lda + acol;
    const float* Bg = Bw + (size_t)(bm0 >> 12) * bstride + (size_t)(bn0 + brow) * CDIM + bcol;
    const uint32_t aS0 = smem_u32(As) + (uint32_t)(arow * LDT + acol) * 4;
    const uint32_t bS0 = smem_u32(Bs) + (uint32_t)(brow * LDT + bcol) * 4;

    const int mi = lane >> 3, mr = lane & 7;
    uint32_t aLd[2];
#pragma unroll
    for (int mf = 0; mf < 2; mf++)
        aLd[mf] = (uint32_t)(((wm + mf * 16 + (mi & 1) * 8 + mr) * LDT + (mi >> 1) * 4) * 4);
    uint32_t bLd[4];
#pragma unroll
    for (int p = 0; p < 4; p++)
        bLd[p] = (uint32_t)(((wn + p * 16 + (mi >> 1) * 8 + mr) * LDT + (mi & 1) * 4) * 4);
    const uint32_t aBase = smem_u32(As), bBase = smem_u32(Bs);

    float acc[2][8][4];
#pragma unroll
    for (int i = 0; i < 2; i++)
#pragma unroll
        for (int j = 0; j < 8; j++)
#pragma unroll
            for (int r = 0; r < 4; r++) acc[i][j][r] = 0.f;

    auto load_stage = [&](int s, int kt) {
        const float* ag = Ag + kt * BK;
        const float* bg = Bg + kt * BK;
        uint32_t ad = aS0 + (uint32_t)(s * BM * LDT) * 4;
        uint32_t bd = bS0 + (uint32_t)(s * BN * LDT) * 4;
#pragma unroll
        for (int j = 0; j < 2; j++) cpasync16(ad + j * 16, ag + j * 4);
#pragma unroll
        for (int j = 0; j < 4; j++) cpasync16(bd + j * 16, bg + j * 4);
    };

    auto compute = [&](int s) {
        const uint32_t aSt = aBase + (uint32_t)(s * BM * LDT) * 4;
        const uint32_t bSt = bBase + (uint32_t)(s * BN * LDT) * 4;
#pragma unroll
        for (int ks = 0; ks < 4; ks++) {
            const uint32_t ko = (uint32_t)(ks * 8 * 4);
            uint32_t af[2][4], bf[8][2];
#pragma unroll
            for (int mf = 0; mf < 2; mf++)
                ldsm4(af[mf], aSt + aLd[mf] + ko);
#pragma unroll
            for (int p = 0; p < 4; p++) {
                uint32_t r[4];
                ldsm4(r, bSt + bLd[p] + ko);
                bf[2 * p][0] = r[0]; bf[2 * p][1] = r[1];
                bf[2 * p + 1][0] = r[2]; bf[2 * p + 1][1] = r[3];
            }
#pragma unroll
            for (int mf = 0; mf < 2; mf++)
#pragma unroll
                for (int nf = 0; nf < 8; nf++)
                    mma_tf32(acc[mf][nf], af[mf], bf[nf]);
        }
    };

    load_stage(0, 0); cp_commit();
    load_stage(1, 1); cp_commit();
    load_stage(2, 2); cp_commit();
    cp_wait2();
    __syncthreads();

    for (int kt = 0; kt < KTILES; kt++) {
        int s = kt % STAGES;
        if (kt + 3 < KTILES) load_stage((kt + 3) % STAGES, kt + 3);
        cp_commit();
        compute(s);
        cp_wait2();
        __syncthreads();
    }

    // ---- epilogue ----
#pragma unroll
    for (int mf = 0; mf < 2; mf++) {
        int r0 = bm0 + wm + mf * 16 + gid;
        float al0 = __ldg(alpha + r0), be0 = __ldg(beta + r0);
        float al1 = __ldg(alpha + r0 + 8), be1 = __ldg(beta + r0 + 8);
        float* crow0 = C + (size_t)r0 * ldc;
        float* crow1 = C + (size_t)(r0 + 8) * ldc;
#pragma unroll
        for (int nf = 0; nf < 8; nf++) {
            int c = bn0 + wn + nf * 8 + tig * 2;
            float q10 = __ldg(p1 + c), q11 = __ldg(p1 + c + 1);
            float q20 = __ldg(p2 + c), q21 = __ldg(p2 + c + 1);
            float v0 = al0 * acc[mf][nf][0] + be0 * q10 + q20;
            float v1 = al0 * acc[mf][nf][1] + be0 * q11 + q21;
            float v2 = al1 * acc[mf][nf][2] + be1 * q10 + q20;
            float v3 = al1 * acc[mf][nf][3] + be1 * q11 + q21;
            if (ROUND) { v0 = tf32f(v0); v1 = tf32f(v1); v2 = tf32f(v2); v3 = tf32f(v3); }
            *(float2*)(crow0 + c) = make_float2(v0, v1);
            *(float2*)(crow1 + c) = make_float2(v2, v3);
        }
    }
}

// ---------------- prep kernels ----------------
// zero s1, s2, kv (atomic targets)
__global__ void zaux_kernel(float* __restrict__ s1, float* __restrict__ s2,
                            float* __restrict__ kv) {
    int i = blockIdx.x * 1024 + threadIdx.x;
    if (i < QKVCOLS) { s1[i] = 0.f; s2[i] = 0.f; }
    if (i < BATCH * EDIM) kv[i] = 0.f;
}

// fused: WgT transpose+round AND colsum s1/s2 (atomic partials)
__global__ void wqkvT_cs_kernel(const float* __restrict__ w, const float* __restrict__ g,
                                const float* __restrict__ b, float* __restrict__ wt,
                                float* __restrict__ s1, float* __restrict__ s2) {
    __shared__ float tg[32][33], tb[32][33];
    __shared__ float rg[8][33], rb[8][33];
    int nb = blockIdx.x * 32, kb = blockIdx.y * 32;
    int tx = threadIdx.x, ty = threadIdx.y;
#pragma unroll
    for (int i = 0; i < 4; i++) {
        int k = kb + ty + i * 8;
        float wv = w[(size_t)k * QKVCOLS + nb + tx];
        tg[ty + i * 8][tx] = g[k] * wv;
        tb[ty + i * 8][tx] = b[k] * wv;
    }
    __syncthreads();
#pragma unroll
    for (int i = 0; i < 4; i++) {
        int n = nb + ty + i * 8;
        wt[(size_t)n * CDIM + kb + tx] = tf32f(tg[tx][ty + i * 8]);
    }
    float sg = 0.f, sb = 0.f;
#pragma unroll
    for (int i = 0; i < 4; i++) { sg += tg[ty + i * 8][tx]; sb += tb[ty + i * 8][tx]; }
    rg[ty][tx] = sg; rb[ty][tx] = sb;
    __syncthreads();
    if (ty == 0) {
        float ag = 0.f, ab = 0.f;
#pragma unroll
        for (int t = 0; t < 8; t++) { ag += rg[t][tx]; ab += rb[t][tx]; }
        atomicAdd(&s1[nb + tx], ag);
        atomicAdd(&s2[nb + tx], ab);
    }
}

// fused: LN stats AND tf32-rounded copy of x
__global__ void ln_stats_round_kernel(const float* __restrict__ x, float* __restrict__ xr,
                                      float* __restrict__ alpha, float* __restrict__ beta) {
    int m = blockIdx.x * 8 + (threadIdx.x >> 5);
    int lane = threadIdx.x & 31;
    const float* row = x + (size_t)m * CDIM;
    float* orow = xr + (size_t)m * CDIM;
    float v[24], s = 0.f;
#pragma unroll
    for (int i = 0; i < 24; i++) { v[i] = row[lane + 32 * i]; s += v[i]; }
#pragma unroll
    for (int i = 0; i < 24; i++) orow[lane + 32 * i] = tf32f(v[i]);
    s = wsum(s);
    float mean = s * (1.0f / CDIM);
    float ss = 0.f;
#pragma unroll
    for (int i = 0; i < 24; i++) { float d = v[i] - mean; ss += d * d; }
    ss = wsum(ss);
    if (lane == 0) {
        float rs = rsqrtf(ss * (1.0f / CDIM) + 1e-5f);
        alpha[m] = rs;
        beta[m] = -mean * rs;
    }
}

__global__ void wprojT_kernel(const float* __restrict__ wp, const float* __restrict__ g2,
                              const float* __restrict__ kv, float* __restrict__ wbt) {
    __shared__ float t[32][33];
    int nb = blockIdx.x * 32, eb = blockIdx.y * 32, b = blockIdx.z;
    int tx = threadIdx.x, ty = threadIdx.y;
#pragma unroll
    for (int i = 0; i < 4; i++) {
        int e = eb + ty + i * 8;
        t[ty + i * 8][tx] = kv[b * EDIM + e] * g2[e] * wp[(size_t)e * CDIM + nb + tx];
    }
    __syncthreads();
#pragma unroll
    for (int i = 0; i < 4; i++) {
        int n = nb + ty + i * 8;
        wbt[((size_t)b * EDIM + n) * EDIM + eb + tx] = tf32f(t[tx][ty + i * 8]);
    }
}

__global__ void colsum2_kernel(const float* __restrict__ wp, const float* __restrict__ g2,
                               const float* __restrict__ b2, float* __restrict__ t1,
                               float* __restrict__ t2) {
    int n = blockIdx.x * 256 + threadIdx.x;
    float a = 0.f, c = 0.f;
    for (int e = 0; e < EDIM; e++) {
        float wv = wp[(size_t)e * CDIM + n];
        a += g2[e] * wv; c += b2[e] * wv;
    }
    t1[n] = a; t2[n] = c;
}

// ---------------- stats kernels ----------------
__global__ void knorm_kernel(const float* __restrict__ qkv, float* __restrict__ invnk) {
    int m = blockIdx.x * 8 + (threadIdx.x >> 5);
    int lane = threadIdx.x & 31;
    const float* row = qkv + (size_t)m * QKVCOLS + EDIM;
    float ss = 0.f;
#pragma unroll
    for (int i = 0; i < 24; i++) { float t = row[lane + 32 * i]; ss += t * t; }
    ss = wsum(ss);
    if (lane == 0) invnk[m] = 1.0f / fmaxf(sqrtf(ss), 1e-12f);
}

__global__ void kv_acc_kernel(const float* __restrict__ qkv,
                              const float* __restrict__ invnk,
                              float* __restrict__ kv) {
    int b = blockIdx.y, chunk = blockIdx.x, tid = threadIdx.x;
    float a0 = 0.f, a1 = 0.f, a2 = 0.f;
    int m0 = b * SEQ + chunk * 128;
    for (int t = 0; t < 128; t++) {
        size_t base = (size_t)(m0 + t) * QKVCOLS;
        float inv = __ldg(invnk + m0 + t);
        const float* kr = qkv + base + EDIM;
        const float* vr = qkv + base + 2 * EDIM;
        a0 += kr[tid] * inv * vr[tid];
        a1 += kr[tid + 256] * inv * vr[tid + 256];
        a2 += kr[tid + 512] * inv * vr[tid + 512];
    }
    atomicAdd(&kv[b * EDIM + tid], a0);
    atomicAdd(&kv[b * EDIM + tid + 256], a1);
    atomicAdd(&kv[b * EDIM + tid + 512], a2);
}

__global__ void qstats_kernel(const float* __restrict__ qkv, const float* __restrict__ kv,
                              float* __restrict__ alpha, float* __restrict__ beta) {
    int m = blockIdx.x * 8 + (threadIdx.x >> 5);
    int lane = threadIdx.x & 31;
    const float* qr = qkv + (size_t)m * QKVCOLS;
    const float* kvr = kv + (m >> 12) * EDIM;
    float sq = 0.f, s1 = 0.f, s2 = 0.f;
#pragma unroll
    for (int i = 0; i < 24; i++) {
        int e = lane + 32 * i;
        float q = qr[e], c = kvr[e];
        sq += q * q;
        float a = q * c;
        s1 += a; s2 += a * a;
    }
    sq = wsum(sq); s1 = wsum(s1); s2 = wsum(s2);
    if (lane == 0) {
        float inv = 1.0f / fmaxf(sqrtf(sq), 1e-12f);
        float mean = s1 * inv * (1.0f / EDIM);
        float msq = s2 * inv * inv * (1.0f / EDIM);
        float var = fmaxf(msq - mean * mean, 0.f);
        float rs2 = rsqrtf(var + 1e-5f);
        alpha[m] = rs2 * inv;
        beta[m] = -mean * rs2;
    }
}

// ---------------- launcher ----------------
extern "C" void kernel_launch(void* const* d_in, const int* in_sizes, int n_in,
                              void* d_out, int out_size) {
    (void)in_sizes; (void)n_in; (void)out_size;
    const float* x      = (const float*)d_in[0];
    const float* w_qkv  = (const float*)d_in[1];
    const float* w_proj = (const float*)d_in[2];
    const float* g_in   = (const float*)d_in[3];
    const float* b_in   = (const float*)d_in[4];
    const float* g_out  = (const float*)d_in[5];
    const float* b_out  = (const float*)d_in[6];
    float* out = (float*)d_out;

    float *qkv, *xr, *wgt, *wbt, *s1, *s2, *t1, *t2, *a1, *be1, *a2, *be2, *invnk, *kv;
    cudaGetSymbolAddress((void**)&qkv, g_qkv);
    cudaGetSymbolAddress((void**)&xr, g_xr);
    cudaGetSymbolAddress((void**)&wgt, g_wgt);
    cudaGetSymbolAddress((void**)&wbt, g_wbt);
    cudaGetSymbolAddress((void**)&s1, g_s1);
    cudaGetSymbolAddress((void**)&s2, g_s2);
    cudaGetSymbolAddress((void**)&t1, g_t1);
    cudaGetSymbolAddress((void**)&t2, g_t2);
    cudaGetSymbolAddress((void**)&a1, g_alpha1);
    cudaGetSymbolAddress((void**)&be1, g_beta1);
    cudaGetSymbolAddress((void**)&a2, g_alpha2);
    cudaGetSymbolAddress((void**)&be2, g_beta2);
    cudaGetSymbolAddress((void**)&invnk, g_invnk);
    cudaGetSymbolAddress((void**)&kv, g_kv);

    cudaFuncSetAttribute(gemm_mma_kernel<1>, cudaFuncAttributeMaxDynamicSharedMemorySize, GEMM_SMEM);
    cudaFuncSetAttribute(gemm_mma_kernel<0>, cudaFuncAttributeMaxDynamicSharedMemorySize, GEMM_SMEM);

    // (1) zero atomic targets
    zaux_kernel<<<(BATCH * EDIM + 1023) / 1024, 1024>>>(s1, s2, kv);
    // (2) fused weight transpose + colsums
    wqkvT_cs_kernel<<<dim3(QKVCOLS / 32, CDIM / 32), dim3(32, 8)>>>(w_qkv, g_in, b_in, wgt, s1, s2);
    // (3) fused LN stats + tf32 rounding of x
    ln_stats_round_kernel<<<MTOK / 8, 256>>>(x, xr, a1, be1);
    // (4) GEMM1 (lands in the ncu capture slot)
    gemm_mma_kernel<1><<<dim3(QKVCOLS / BN, MTOK / BM), GTHR, GEMM_SMEM>>>(
        xr, CDIM, wgt, 0, qkv, QKVCOLS, a1, be1, s1, s2);
    // (5-7) kv pipeline
    knorm_kernel<<<MTOK / 8, 256>>>(qkv, invnk);
    kv_acc_kernel<<<dim3(SEQ / 128, BATCH), 256>>>(qkv, invnk, kv);
    qstats_kernel<<<MTOK / 8, 256>>>(qkv, kv, a2, be2);
    // (8-9) GEMM2 weights
    wprojT_kernel<<<dim3(CDIM / 32, EDIM / 32, BATCH), dim3(32, 8)>>>(w_proj, g_out, kv, wbt);
    colsum2_kernel<<<CDIM / 256, 256>>>(w_proj, g_out, b_out, t1, t2);
    // (10) GEMM2
    gemm_mma_kernel<0><<<dim3(CDIM / BN, MTOK / BM), GTHR, GEMM_SMEM>>>(
        qkv, QKVCOLS, wbt, (size_t)EDIM * EDIM, out, CDIM, a2, be2, t1, t2);
}